// round 1
// baseline (speedup 1.0000x reference)
#include <cuda_runtime.h>
#include <cuda_bf16.h>

// Problem shapes (fixed by setup_inputs)
#define N_ROWS 8192
#define M_ROWS 16384
#define DIM    256

#define BN 64
#define BM 64
#define BK 32
#define SPLITS 8
#define MCHUNK (M_ROWS / SPLITS)   // 2048

// Scratch (no cudaMalloc allowed)
__device__ float g_An[N_ROWS * DIM];            // 8.4 MB
__device__ float g_Bn[M_ROWS * DIM];            // 16.8 MB
__device__ float g_part[N_ROWS * SPLITS * 3];   // 0.8 MB

// ---------------------------------------------------------------------------
// Row L2-normalization: one block per row, 256 threads (one per element)
// ---------------------------------------------------------------------------
__global__ void normalize_rows(const float* __restrict__ in,
                               float* __restrict__ out) {
    int row = blockIdx.x;
    int tid = threadIdx.x;
    float v = in[row * DIM + tid];
    float s = v * v;
    // warp reduce
    #pragma unroll
    for (int o = 16; o > 0; o >>= 1)
        s += __shfl_xor_sync(0xFFFFFFFFu, s, o);
    __shared__ float red[8];
    int wid = tid >> 5;
    if ((tid & 31) == 0) red[wid] = s;
    __syncthreads();
    __shared__ float total_sh;
    if (tid < 32) {
        float t = (tid < 8) ? red[tid] : 0.0f;
        #pragma unroll
        for (int o = 4; o > 0; o >>= 1)
            t += __shfl_xor_sync(0xFFFFFFFFu, t, o);
        if (tid == 0) total_sh = t;
    }
    __syncthreads();
    out[row * DIM + tid] = v * rsqrtf(total_sh);
}

// ---------------------------------------------------------------------------
// Fused SGEMM + running top-3.
// Grid: (N_ROWS/BN, SPLITS). Block: 256 threads.
// Each block: 64 N-rows x 2048 M-cols, K=256.
// ---------------------------------------------------------------------------
__device__ __forceinline__ void top3_insert(float v, float& t0, float& t1, float& t2) {
    if (v > t2) {
        if (v > t0)      { t2 = t1; t1 = t0; t0 = v; }
        else if (v > t1) { t2 = t1; t1 = v; }
        else             { t2 = v; }
    }
}

__global__ __launch_bounds__(256, 2)
void gemm_top3(const float* __restrict__ A,   // [N,256] normalized
               const float* __restrict__ B,   // [M,256] normalized
               float* __restrict__ part) {    // [N][SPLITS][3]
    __shared__ float sA[BK][BN];
    __shared__ float sB[BK][BM];
    __shared__ float sS[BN][BM + 4];
    __shared__ float cand[BN][4][3];

    const int tid = threadIdx.x;          // 0..255
    const int tx = tid & 15;              // M micro-tile index
    const int ty = tid >> 4;              // N micro-tile index
    const int nBase = blockIdx.x * BN;
    const int mBase = blockIdx.y * MCHUNK;

    // scan assignment: 4 threads per row, 16 cols each
    const int scanRow = tid >> 2;         // 0..63
    const int scanCol = (tid & 3) * 16;   // 0,16,32,48

    float t0 = -2.0f, t1 = -2.0f, t2 = -2.0f;

    for (int mt = 0; mt < MCHUNK; mt += BM) {
        float acc[4][4];
        #pragma unroll
        for (int i = 0; i < 4; i++)
            #pragma unroll
            for (int j = 0; j < 4; j++) acc[i][j] = 0.0f;

        #pragma unroll
        for (int k0 = 0; k0 < DIM; k0 += BK) {
            // Load A tile (64 rows x 32 k) transposed into sA[k][n]
            #pragma unroll
            for (int l = 0; l < 2; l++) {
                int idx = tid + l * 256;       // 0..511 float4 slots
                int n   = idx >> 3;            // row within tile
                int kq  = (idx & 7) * 4;       // k offset
                float4 v = *(const float4*)&A[(size_t)(nBase + n) * DIM + k0 + kq];
                sA[kq + 0][n] = v.x; sA[kq + 1][n] = v.y;
                sA[kq + 2][n] = v.z; sA[kq + 3][n] = v.w;
            }
            // Load B tile likewise
            #pragma unroll
            for (int l = 0; l < 2; l++) {
                int idx = tid + l * 256;
                int m   = idx >> 3;
                int kq  = (idx & 7) * 4;
                float4 v = *(const float4*)&B[(size_t)(mBase + mt + m) * DIM + k0 + kq];
                sB[kq + 0][m] = v.x; sB[kq + 1][m] = v.y;
                sB[kq + 2][m] = v.z; sB[kq + 3][m] = v.w;
            }
            __syncthreads();

            #pragma unroll
            for (int kk = 0; kk < BK; kk++) {
                float a[4], b[4];
                #pragma unroll
                for (int i = 0; i < 4; i++) a[i] = sA[kk][ty * 4 + i];
                #pragma unroll
                for (int j = 0; j < 4; j++) b[j] = sB[kk][tx * 4 + j];
                #pragma unroll
                for (int i = 0; i < 4; i++)
                    #pragma unroll
                    for (int j = 0; j < 4; j++)
                        acc[i][j] = fmaf(a[i], b[j], acc[i][j]);
            }
            __syncthreads();
        }

        // Stage scores to smem, then fold into running top-3
        #pragma unroll
        for (int i = 0; i < 4; i++) {
            #pragma unroll
            for (int j = 0; j < 4; j++)
                sS[ty * 4 + i][tx * 4 + j] = acc[i][j];
        }
        __syncthreads();
        #pragma unroll
        for (int c = 0; c < 16; c++) {
            float v = sS[scanRow][scanCol + c];
            top3_insert(v, t0, t1, t2);
        }
        __syncthreads();
    }

    // Merge 4 threads' top-3 per row
    cand[scanRow][tid & 3][0] = t0;
    cand[scanRow][tid & 3][1] = t1;
    cand[scanRow][tid & 3][2] = t2;
    __syncthreads();
    if (tid < BN) {
        float m0 = -2.0f, m1 = -2.0f, m2 = -2.0f;
        #pragma unroll
        for (int g = 0; g < 4; g++)
            #pragma unroll
            for (int s = 0; s < 3; s++)
                top3_insert(cand[tid][g][s], m0, m1, m2);
        size_t o = ((size_t)(nBase + tid) * SPLITS + blockIdx.y) * 3;
        part[o + 0] = m0; part[o + 1] = m1; part[o + 2] = m2;
    }
}

// ---------------------------------------------------------------------------
// Final merge across splits + mean
// ---------------------------------------------------------------------------
__global__ void merge_top3(const float* __restrict__ part,
                           float* __restrict__ out) {
    int n = blockIdx.x * blockDim.x + threadIdx.x;
    if (n >= N_ROWS) return;
    float t0 = -2.0f, t1 = -2.0f, t2 = -2.0f;
    const float* p = part + (size_t)n * SPLITS * 3;
    #pragma unroll
    for (int i = 0; i < SPLITS * 3; i++)
        top3_insert(p[i], t0, t1, t2);
    out[n] = (t0 + t1 + t2) * (1.0f / 3.0f);
}

// ---------------------------------------------------------------------------
extern "C" void kernel_launch(void* const* d_in, const int* in_sizes, int n_in,
                              void* d_out, int out_size) {
    const float* A = (const float*)d_in[0];   // tensor_1 [8192,256]
    const float* B = (const float*)d_in[1];   // tensor_2 [16384,256]
    float* out = (float*)d_out;

    float* An;  cudaGetSymbolAddress((void**)&An,  g_An);
    float* Bn;  cudaGetSymbolAddress((void**)&Bn,  g_Bn);
    float* prt; cudaGetSymbolAddress((void**)&prt, g_part);

    normalize_rows<<<N_ROWS, DIM>>>(A, An);
    normalize_rows<<<M_ROWS, DIM>>>(B, Bn);

    dim3 grid(N_ROWS / BN, SPLITS);
    gemm_top3<<<grid, 256>>>(An, Bn, prt);

    merge_top3<<<(N_ROWS + 255) / 256, 256>>>(prt, out);
}

// round 5
// speedup vs baseline: 3.0049x; 3.0049x over previous
#include <cuda_runtime.h>
#include <cstdint>

// ---------------- problem shapes (fixed) ----------------
#define N_ROWS 8192
#define M_ROWS 16384
#define DIM    256

#define BM 128                      // A rows per CTA
#define BN 128                      // B rows per tile
#define SPLITS 16
#define BROWS (M_ROWS / SPLITS)     // 1024 B rows per CTA
#define NBT   (BROWS / BN)          // 8 tiles
#define KCH   32                    // K floats per cp.async chunk
#define TOTCH (NBT * (DIM / KCH))   // 64 chunks

#define SMEM_FLOATS (BM * DIM + 2 * BM * KCH)       // 32768 + 8192
#define SMEM_BYTES  (SMEM_FLOATS * 4)               // 163840

// ---------------- scratch (no cudaMalloc allowed) ----------------
__device__ float g_An[N_ROWS * DIM];
__device__ float g_Bn[M_ROWS * DIM];
__device__ float g_part[N_ROWS * SPLITS * 3];

// ---------------- helpers ----------------
__device__ __forceinline__ uint32_t smem_u32(const void* p) {
    uint32_t a;
    asm("{ .reg .u64 t; cvta.to.shared.u64 t, %1; cvt.u32.u64 %0, t; }" : "=r"(a) : "l"(p));
    return a;
}
__device__ __forceinline__ void cp_async16(uint32_t dst, const void* src) {
    asm volatile("cp.async.cg.shared.global [%0], [%1], 16;" :: "r"(dst), "l"(src));
}
#define CP_COMMIT()  asm volatile("cp.async.commit_group;" ::: "memory")
#define CP_WAIT(n)   asm volatile("cp.async.wait_group %0;" :: "n"(n) : "memory")

__device__ __forceinline__ void mma_tf32(float* d, const float* a, const float* b) {
    asm volatile(
        "mma.sync.aligned.m16n8k8.row.col.f32.tf32.tf32.f32 "
        "{%0,%1,%2,%3},{%4,%5,%6,%7},{%8,%9},{%0,%1,%2,%3};"
        : "+f"(d[0]), "+f"(d[1]), "+f"(d[2]), "+f"(d[3])
        : "r"(__float_as_uint(a[0])), "r"(__float_as_uint(a[1])),
          "r"(__float_as_uint(a[2])), "r"(__float_as_uint(a[3])),
          "r"(__float_as_uint(b[0])), "r"(__float_as_uint(b[1])));
}

// ---------------- row L2 normalization (+ tf32 RNA rounding) ----------------
__global__ void normalize_rows(const float* __restrict__ in, float* __restrict__ out) {
    int row = blockIdx.x, tid = threadIdx.x;
    float v = in[row * DIM + tid];
    float s = v * v;
    #pragma unroll
    for (int o = 16; o > 0; o >>= 1) s += __shfl_xor_sync(0xFFFFFFFFu, s, o);
    __shared__ float red[8];
    if ((tid & 31) == 0) red[tid >> 5] = s;
    __syncthreads();
    __shared__ float tot;
    if (tid < 32) {
        float t = (tid < 8) ? red[tid] : 0.0f;
        #pragma unroll
        for (int o = 4; o > 0; o >>= 1) t += __shfl_xor_sync(0xFFFFFFFFu, t, o);
        if (tid == 0) tot = t;
    }
    __syncthreads();
    float y = v * rsqrtf(tot);
    uint32_t r;
    asm("cvt.rna.tf32.f32 %0, %1;" : "=r"(r) : "f"(y));   // pre-round: mma truncation becomes no-op
    out[row * DIM + tid] = __uint_as_float(r);
}

// ---------------- fused tf32 mma.sync GEMM + top-3 ----------------
__global__ void __launch_bounds__(256, 1)
gemm_top3(const float* __restrict__ A, const float* __restrict__ B,
          float* __restrict__ part) {
    extern __shared__ float smem[];
    float* sA = smem;                 // [128][256] fp32(tf32), float4-XOR swizzled
    float* sB = smem + BM * DIM;      // 2 x [128][32]
    const uint32_t sAu = smem_u32(sA);
    const uint32_t sBu = smem_u32(sB);

    const int tid  = threadIdx.x;
    const int w    = tid >> 5, lane = tid & 31;
    const int ty   = lane >> 2, tx = lane & 3;
    const int warpM = w >> 2, warpN = w & 3;     // 2 x 4 warp grid

    const int aBase = blockIdx.x * BM;
    const int bBase = blockIdx.y * BROWS;

    // ---- A tile: 128 rows x 256 floats, swizzle f' = f ^ (row&7) at float4 grain ----
    #pragma unroll 4
    for (int i = tid; i < BM * DIM / 4; i += 256) {
        int r = i >> 6, f = i & 63;
        uint32_t dst = sAu + (uint32_t)((r * 256 + ((f ^ (r & 7)) << 2)) * 4);
        cp_async16(dst, &A[(size_t)(aBase + r) * DIM + f * 4]);
    }
    CP_COMMIT();

    // ---- issue B chunk helper (as a lambda-free macro-ish block) ----
    auto issueB = [&](int c) {
        int t = c >> 3, kc = c & 7, buf = c & 1;
        #pragma unroll 4
        for (int i = tid; i < BM * KCH / 4; i += 256) {
            int n = i >> 3, f = i & 7;
            uint32_t dst = sBu + (uint32_t)(((buf * BM * KCH) + n * 32 + ((f ^ (n & 7)) << 2)) * 4);
            cp_async16(dst, &B[(size_t)(bBase + t * BN + n) * DIM + kc * KCH + f * 4]);
        }
    };

    issueB(0);
    CP_COMMIT();

    float acc[4][4][4];
    #pragma unroll
    for (int m = 0; m < 4; m++)
        #pragma unroll
        for (int nt = 0; nt < 4; nt++)
            #pragma unroll
            for (int q = 0; q < 4; q++) acc[m][nt][q] = 0.0f;

    float s0[8], s1[8], s2[8];
    #pragma unroll
    for (int i = 0; i < 8; i++) { s0[i] = -2.0f; s1[i] = -2.0f; s2[i] = -2.0f; }

    for (int c = 0; c < TOTCH; c++) {
        if (c + 1 < TOTCH) { issueB(c + 1); CP_COMMIT(); CP_WAIT(1); }
        else               { CP_WAIT(0); }
        __syncthreads();

        const float* bb = sB + (c & 1) * BM * KCH;
        const int kc = c & 7;

        #pragma unroll
        for (int ks = 0; ks < 4; ks++) {
            const int kg = kc * 32 + ks * 8;
            const int f0 = kg >> 2;              // even float4 index
            float a[4][4];
            #pragma unroll
            for (int m = 0; m < 4; m++) {
                int r0 = warpM * 64 + m * 16 + ty;
                int r1 = r0 + 8;
                const float* p0 = sA + r0 * 256;
                const float* p1 = sA + r1 * 256;
                a[m][0] = p0[((f0 ^ (r0 & 7)) << 2) + tx];
                a[m][1] = p1[((f0 ^ (r1 & 7)) << 2) + tx];
                a[m][2] = p0[(((f0 + 1) ^ (r0 & 7)) << 2) + tx];
                a[m][3] = p1[(((f0 + 1) ^ (r1 & 7)) << 2) + tx];
            }
            float b[4][2];
            #pragma unroll
            for (int nt = 0; nt < 4; nt++) {
                int n = warpN * 32 + nt * 8 + ty;
                const float* pb = bb + n * 32;
                int fb = ks * 2;
                b[nt][0] = pb[((fb ^ (n & 7)) << 2) + tx];
                b[nt][1] = pb[(((fb + 1) ^ (n & 7)) << 2) + tx];
            }
            #pragma unroll
            for (int m = 0; m < 4; m++)
                #pragma unroll
                for (int nt = 0; nt < 4; nt++)
                    mma_tf32(acc[m][nt], a[m], b[nt]);
        }
        __syncthreads();

        if ((c & 7) == 7) {
            // fold 128x128 tile into running top-3, then clear accumulators
            #pragma unroll
            for (int m = 0; m < 4; m++) {
                #pragma unroll
                for (int h = 0; h < 2; h++) {
                    const int sIdx = m * 2 + h;
                    float v[8];
                    #pragma unroll
                    for (int nt = 0; nt < 4; nt++) {
                        v[nt * 2 + 0] = acc[m][nt][h * 2 + 0];
                        v[nt * 2 + 1] = acc[m][nt][h * 2 + 1];
                    }
                    float bm = v[0];
                    #pragma unroll
                    for (int q = 1; q < 8; q++) bm = fmaxf(bm, v[q]);
                    if (bm > s2[sIdx]) {
                        #pragma unroll
                        for (int q = 0; q < 8; q++) {
                            float x = v[q];
                            s2[sIdx] = fmaxf(s2[sIdx], fminf(x, s1[sIdx]));
                            s1[sIdx] = fmaxf(s1[sIdx], fminf(x, s0[sIdx]));
                            s0[sIdx] = fmaxf(s0[sIdx], x);
                        }
                    }
                }
            }
            #pragma unroll
            for (int m = 0; m < 4; m++)
                #pragma unroll
                for (int nt = 0; nt < 4; nt++)
                    #pragma unroll
                    for (int q = 0; q < 4; q++) acc[m][nt][q] = 0.0f;
        }
    }

    // ---- merge per-row candidates (4 lanes x 4 N-warps = 16 contributors) ----
    __syncthreads();
    float* cand = smem;   // reuse: [128 rows][16 contrib][3]
    #pragma unroll
    for (int m = 0; m < 4; m++) {
        #pragma unroll
        for (int h = 0; h < 2; h++) {
            const int sIdx = m * 2 + h;
            int row = warpM * 64 + m * 16 + h * 8 + ty;
            int ct  = warpN * 4 + tx;
            float* p = cand + (row * 16 + ct) * 3;
            p[0] = s0[sIdx]; p[1] = s1[sIdx]; p[2] = s2[sIdx];
        }
    }
    __syncthreads();
    if (tid < BM) {
        const float* p = cand + tid * 48;
        float t0 = -2.0f, t1 = -2.0f, t2 = -2.0f;
        #pragma unroll
        for (int i = 0; i < 48; i++) {
            float x = p[i];
            t2 = fmaxf(t2, fminf(x, t1));
            t1 = fmaxf(t1, fminf(x, t0));
            t0 = fmaxf(t0, x);
        }
        size_t row = (size_t)(blockIdx.x * BM + tid);
        size_t o = (row * SPLITS + blockIdx.y) * 3;
        part[o + 0] = t0; part[o + 1] = t1; part[o + 2] = t2;
    }
}

// ---------------- merge splits + mean ----------------
__global__ void merge_top3(const float* __restrict__ part, float* __restrict__ out) {
    int n = blockIdx.x * blockDim.x + threadIdx.x;
    if (n >= N_ROWS) return;
    const float* p = part + (size_t)n * SPLITS * 3;
    float t0 = -2.0f, t1 = -2.0f, t2 = -2.0f;
    #pragma unroll
    for (int i = 0; i < SPLITS * 3; i++) {
        float v = p[i];
        t2 = fmaxf(t2, fminf(v, t1));
        t1 = fmaxf(t1, fminf(v, t0));
        t0 = fmaxf(t0, v);
    }
    out[n] = (t0 + t1 + t2) * (1.0f / 3.0f);
}

// ---------------- launcher ----------------
extern "C" void kernel_launch(void* const* d_in, const int* in_sizes, int n_in,
                              void* d_out, int out_size) {
    const float* A = (const float*)d_in[0];
    const float* B = (const float*)d_in[1];
    float* out = (float*)d_out;

    float* An;  cudaGetSymbolAddress((void**)&An,  g_An);
    float* Bn;  cudaGetSymbolAddress((void**)&Bn,  g_Bn);
    float* prt; cudaGetSymbolAddress((void**)&prt, g_part);

    cudaFuncSetAttribute(gemm_top3, cudaFuncAttributeMaxDynamicSharedMemorySize, SMEM_BYTES);

    normalize_rows<<<N_ROWS, DIM>>>(A, An);
    normalize_rows<<<M_ROWS, DIM>>>(B, Bn);

    dim3 grid(N_ROWS / BM, SPLITS);
    gemm_top3<<<grid, 256, SMEM_BYTES>>>(An, Bn, prt);

    merge_top3<<<(N_ROWS + 255) / 256, 256>>>(prt, out);
}

// round 6
// speedup vs baseline: 5.9414x; 1.9772x over previous
#include <cuda_runtime.h>
#include <cuda_bf16.h>
#include <cstdint>

// ---------------- problem shapes (fixed) ----------------
#define N_ROWS 8192
#define M_ROWS 16384
#define DIM    256

#define BM 128
#define BN 128
#define SPLITS 16
#define BROWS (M_ROWS / SPLITS)     // 1024
#define NBT   (BROWS / BN)          // 8 tiles
#define KCH   64                    // bf16 K-elems per chunk (128B/row)
#define CPT   (DIM / KCH)           // 4 chunks per tile
#define TOTCH (NBT * CPT)           // 32
#define NBUF  4

// smem (uint32 words): A = 128 rows x 128 words; B = 4 bufs x 128 rows x 32 words
#define AW 128
#define BW 32
#define SMEM_WORDS (BM * AW + NBUF * BM * BW)   // 32768
#define SMEM_BYTES (SMEM_WORDS * 4)             // 131072

// ---------------- scratch ----------------
__device__ float          g_An[N_ROWS * DIM];
__device__ float          g_Bn[M_ROWS * DIM];
__device__ __nv_bfloat16  g_Ah[N_ROWS * DIM];
__device__ __nv_bfloat16  g_Bh[M_ROWS * DIM];
__device__ float          g_partv[N_ROWS * SPLITS * 3];
__device__ int            g_parti[N_ROWS * SPLITS * 3];

// ---------------- helpers ----------------
__device__ __forceinline__ uint32_t smem_u32(const void* p) {
    uint32_t a;
    asm("{ .reg .u64 t; cvta.to.shared.u64 t, %1; cvt.u32.u64 %0, t; }" : "=r"(a) : "l"(p));
    return a;
}
__device__ __forceinline__ void cp_async16(uint32_t dst, const void* src) {
    asm volatile("cp.async.cg.shared.global [%0], [%1], 16;" :: "r"(dst), "l"(src));
}
#define CP_COMMIT()  asm volatile("cp.async.commit_group;" ::: "memory")
#define CP_WAIT(n)   asm volatile("cp.async.wait_group %0;" :: "n"(n) : "memory")

__device__ __forceinline__ void mma_bf16(float* d, const uint32_t* a, const uint32_t* b) {
    asm volatile(
        "mma.sync.aligned.m16n8k16.row.col.f32.bf16.bf16.f32 "
        "{%0,%1,%2,%3},{%4,%5,%6,%7},{%8,%9},{%0,%1,%2,%3};"
        : "+f"(d[0]), "+f"(d[1]), "+f"(d[2]), "+f"(d[3])
        : "r"(a[0]), "r"(a[1]), "r"(a[2]), "r"(a[3]), "r"(b[0]), "r"(b[1]));
}

// ---------------- row L2 normalization: write fp32 (exact) + bf16 ----------------
__global__ void normalize_rows(const float* __restrict__ in,
                               float* __restrict__ outf,
                               __nv_bfloat16* __restrict__ outh) {
    int row = blockIdx.x, tid = threadIdx.x;
    float v = in[row * DIM + tid];
    float s = v * v;
    #pragma unroll
    for (int o = 16; o > 0; o >>= 1) s += __shfl_xor_sync(0xFFFFFFFFu, s, o);
    __shared__ float red[8];
    if ((tid & 31) == 0) red[tid >> 5] = s;
    __syncthreads();
    __shared__ float tot;
    if (tid < 32) {
        float t = (tid < 8) ? red[tid] : 0.0f;
        #pragma unroll
        for (int o = 4; o > 0; o >>= 1) t += __shfl_xor_sync(0xFFFFFFFFu, t, o);
        if (tid == 0) tot = t;
    }
    __syncthreads();
    float y = v * rsqrtf(tot);
    outf[row * DIM + tid] = y;
    outh[row * DIM + tid] = __float2bfloat16(y);
}

// ---------------- bf16 mma GEMM + top-3 (with column indices) ----------------
__global__ void __launch_bounds__(256, 1)
gemm_top3(const __nv_bfloat16* __restrict__ Ah, const __nv_bfloat16* __restrict__ Bh,
          float* __restrict__ partv, int* __restrict__ parti) {
    extern __shared__ uint32_t smem[];
    uint32_t* sA = smem;
    uint32_t* sB = smem + BM * AW;
    const uint32_t sAu = smem_u32(sA);
    const uint32_t sBu = smem_u32(sB);

    const int tid  = threadIdx.x;
    const int w    = tid >> 5, lane = tid & 31;
    const int ty   = lane >> 2, tx = lane & 3;
    const int warpM = w >> 2, warpN = w & 3;

    const int aBase = blockIdx.x * BM;
    const int bBase = blockIdx.y * BROWS;

    // ---- A tile: 128 rows x 256 bf16; word-swizzle iw' = iw ^ ((r&7)<<2) ----
    #pragma unroll 4
    for (int i = tid; i < BM * 32; i += 256) {          // 16B units
        int r = i >> 5, f = i & 31;
        uint32_t dw = (uint32_t)(r * AW + ((4 * f) ^ ((r & 7) << 2)));
        cp_async16(sAu + dw * 4, Ah + (size_t)(aBase + r) * DIM + f * 8);
    }
    CP_COMMIT();

    auto issueB = [&](int c) {
        int t = c >> 2, kc = c & 3, buf = c & 3;
        #pragma unroll 4
        for (int i = tid; i < BM * 8; i += 256) {       // 16B units
            int n = i >> 3, f = i & 7;
            uint32_t dw = (uint32_t)(buf * BM * BW + n * BW + ((4 * f) ^ ((n & 7) << 2)));
            cp_async16(sBu + dw * 4,
                       Bh + (size_t)(bBase + t * BN + n) * DIM + kc * KCH + f * 8);
        }
        CP_COMMIT();
    };

    issueB(0); issueB(1); issueB(2);

    float acc[4][4][4];
    #pragma unroll
    for (int m = 0; m < 4; m++)
        #pragma unroll
        for (int nt = 0; nt < 4; nt++)
            #pragma unroll
            for (int q = 0; q < 4; q++) acc[m][nt][q] = 0.0f;

    float s0[8], s1[8], s2[8];
    int   i0[8], i1[8], i2[8];
    #pragma unroll
    for (int i = 0; i < 8; i++) {
        s0[i] = -2.0f; s1[i] = -2.0f; s2[i] = -2.0f;
        i0[i] = 0; i1[i] = 0; i2[i] = 0;
    }

    for (int c = 0; c < TOTCH; c++) {
        CP_WAIT(2);                  // group c complete (pending <= {c+1, c+2})
        __syncthreads();             // all threads done with buf (c+3)%4's previous contents
        if (c + 3 < TOTCH) issueB(c + 3);
        else CP_COMMIT();            // keep group accounting consistent at tail

        const uint32_t* bb = sB + (c & 3) * BM * BW;

        #pragma unroll
        for (int ks = 0; ks < 4; ks++) {
            const int wA = (c & 3) * 32 + ks * 8 + tx;
            uint32_t a[4][4];
            #pragma unroll
            for (int m = 0; m < 4; m++) {
                int r0 = warpM * 64 + m * 16 + ty;
                int r1 = r0 + 8;
                const uint32_t* p0 = sA + r0 * AW;
                const uint32_t* p1 = sA + r1 * AW;
                const int sw = (ty & 7) << 2;
                a[m][0] = p0[wA ^ sw];
                a[m][1] = p1[wA ^ sw];
                a[m][2] = p0[(wA + 4) ^ sw];
                a[m][3] = p1[(wA + 4) ^ sw];
            }
            uint32_t b[4][2];
            #pragma unroll
            for (int nt = 0; nt < 4; nt++) {
                int n = warpN * 32 + nt * 8 + ty;
                const uint32_t* pb = bb + n * BW;
                const int sw = (n & 7) << 2;
                const int wB = ks * 8 + tx;
                b[nt][0] = pb[wB ^ sw];
                b[nt][1] = pb[(wB + 4) ^ sw];
            }
            #pragma unroll
            for (int m = 0; m < 4; m++)
                #pragma unroll
                for (int nt = 0; nt < 4; nt++)
                    mma_bf16(acc[m][nt], a[m], b[nt]);
        }

        if ((c & 3) == 3) {
            const int tcol = bBase + (c >> 2) * BN + warpN * 32 + tx * 2;
            #pragma unroll
            for (int m = 0; m < 4; m++) {
                #pragma unroll
                for (int h = 0; h < 2; h++) {
                    const int sl = m * 2 + h;
                    float bm = acc[m][0][h * 2];
                    #pragma unroll
                    for (int nt = 0; nt < 4; nt++) {
                        bm = fmaxf(bm, acc[m][nt][h * 2 + 0]);
                        bm = fmaxf(bm, acc[m][nt][h * 2 + 1]);
                    }
                    if (bm > s2[sl]) {
                        #pragma unroll
                        for (int nt = 0; nt < 4; nt++) {
                            #pragma unroll
                            for (int p = 0; p < 2; p++) {
                                float v = acc[m][nt][h * 2 + p];
                                int col = tcol + nt * 8 + p;
                                if (v > s2[sl]) {
                                    if (v > s1[sl]) {
                                        if (v > s0[sl]) {
                                            s2[sl] = s1[sl]; i2[sl] = i1[sl];
                                            s1[sl] = s0[sl]; i1[sl] = i0[sl];
                                            s0[sl] = v;      i0[sl] = col;
                                        } else {
                                            s2[sl] = s1[sl]; i2[sl] = i1[sl];
                                            s1[sl] = v;      i1[sl] = col;
                                        }
                                    } else {
                                        s2[sl] = v; i2[sl] = col;
                                    }
                                }
                            }
                        }
                    }
                }
            }
            #pragma unroll
            for (int m = 0; m < 4; m++)
                #pragma unroll
                for (int nt = 0; nt < 4; nt++)
                    #pragma unroll
                    for (int q = 0; q < 4; q++) acc[m][nt][q] = 0.0f;
        }
    }

    // ---- CTA-level merge: 16 contributors per row -> top-3 (val+idx) ----
    __syncthreads();
    float* candV = (float*)smem;                 // [128][16][3]
    int*   candI = (int*)(smem + 6144);          // [128][16][3]
    #pragma unroll
    for (int m = 0; m < 4; m++) {
        #pragma unroll
        for (int h = 0; h < 2; h++) {
            const int sl = m * 2 + h;
            int row = warpM * 64 + m * 16 + h * 8 + ty;
            int ct  = warpN * 4 + tx;
            int o = (row * 16 + ct) * 3;
            candV[o + 0] = s0[sl]; candV[o + 1] = s1[sl]; candV[o + 2] = s2[sl];
            candI[o + 0] = i0[sl]; candI[o + 1] = i1[sl]; candI[o + 2] = i2[sl];
        }
    }
    __syncthreads();
    if (tid < BM) {
        const float* pv = candV + tid * 48;
        const int*   pi = candI + tid * 48;
        float t0 = -2.0f, t1 = -2.0f, t2 = -2.0f;
        int   j0 = 0, j1 = 0, j2 = 0;
        #pragma unroll
        for (int i = 0; i < 48; i++) {
            float v = pv[i]; int ix = pi[i];
            if (v > t2) {
                if (v > t1) {
                    if (v > t0) { t2 = t1; j2 = j1; t1 = t0; j1 = j0; t0 = v; j0 = ix; }
                    else        { t2 = t1; j2 = j1; t1 = v;  j1 = ix; }
                } else          { t2 = v; j2 = ix; }
            }
        }
        size_t row = (size_t)(blockIdx.x * BM + tid);
        size_t o = (row * SPLITS + blockIdx.y) * 3;
        partv[o + 0] = t0; partv[o + 1] = t1; partv[o + 2] = t2;
        parti[o + 0] = j0; parti[o + 1] = j1; parti[o + 2] = j2;
    }
}

// ---------------- final: top-8 of 48 candidates, exact fp32 rescore, mean top-3 ----
__device__ __forceinline__ unsigned long long mk_key(float v, int idx) {
    uint32_t u = __float_as_uint(v);
    u = (u & 0x80000000u) ? ~u : (u | 0x80000000u);
    return ((unsigned long long)u << 32) | (uint32_t)idx;
}

__global__ void rescore_top3(const float* __restrict__ partv, const int* __restrict__ parti,
                             const float* __restrict__ An, const float* __restrict__ Bn,
                             float* __restrict__ out) {
    const int warp = (blockIdx.x * blockDim.x + threadIdx.x) >> 5;
    const int lane = threadIdx.x & 31;
    if (warp >= N_ROWS) return;
    const int row = warp;

    const float* pv = partv + (size_t)row * 48;
    const int*   pi = parti + (size_t)row * 48;
    unsigned long long k0 = mk_key(pv[lane], pi[lane]);
    unsigned long long k1 = (lane < 16) ? mk_key(pv[32 + lane], pi[32 + lane]) : 0ull;

    int win[8];
    #pragma unroll
    for (int r = 0; r < 8; r++) {
        unsigned long long m = (k0 > k1) ? k0 : k1;
        #pragma unroll
        for (int o = 16; o > 0; o >>= 1) {
            unsigned long long t = __shfl_xor_sync(0xFFFFFFFFu, m, o);
            if (t > m) m = t;
        }
        win[r] = (int)(uint32_t)m;
        if (k0 == m) k0 = 0ull;
        if (k1 == m) k1 = 0ull;
    }

    const float4* a4 = (const float4*)(An + (size_t)row * DIM);
    float4 av0 = a4[lane * 2], av1 = a4[lane * 2 + 1];

    float dots[8];
    #pragma unroll
    for (int j = 0; j < 8; j++) {
        const float4* b4 = (const float4*)(Bn + (size_t)win[j] * DIM);
        float4 b0 = b4[lane * 2], b1 = b4[lane * 2 + 1];
        float p = av0.x * b0.x + av0.y * b0.y + av0.z * b0.z + av0.w * b0.w
                + av1.x * b1.x + av1.y * b1.y + av1.z * b1.z + av1.w * b1.w;
        #pragma unroll
        for (int o = 16; o > 0; o >>= 1) p += __shfl_xor_sync(0xFFFFFFFFu, p, o);
        dots[j] = p;
    }

    if (lane == 0) {
        float t0 = -2.0f, t1 = -2.0f, t2 = -2.0f;
        #pragma unroll
        for (int j = 0; j < 8; j++) {
            float v = dots[j];
            t2 = fmaxf(t2, fminf(v, t1));
            t1 = fmaxf(t1, fminf(v, t0));
            t0 = fmaxf(t0, v);
        }
        out[row] = (t0 + t1 + t2) * (1.0f / 3.0f);
    }
}

// ---------------- launcher ----------------
extern "C" void kernel_launch(void* const* d_in, const int* in_sizes, int n_in,
                              void* d_out, int out_size) {
    const float* A = (const float*)d_in[0];
    const float* B = (const float*)d_in[1];
    float* out = (float*)d_out;

    float* An;  cudaGetSymbolAddress((void**)&An,  g_An);
    float* Bn;  cudaGetSymbolAddress((void**)&Bn,  g_Bn);
    __nv_bfloat16* Ah; cudaGetSymbolAddress((void**)&Ah, g_Ah);
    __nv_bfloat16* Bh; cudaGetSymbolAddress((void**)&Bh, g_Bh);
    float* pv;  cudaGetSymbolAddress((void**)&pv, g_partv);
    int*   pi;  cudaGetSymbolAddress((void**)&pi, g_parti);

    cudaFuncSetAttribute(gemm_top3, cudaFuncAttributeMaxDynamicSharedMemorySize, SMEM_BYTES);

    normalize_rows<<<N_ROWS, DIM>>>(A, An, Ah);
    normalize_rows<<<M_ROWS, DIM>>>(B, Bn, Bh);

    dim3 grid(N_ROWS / BM, SPLITS);
    gemm_top3<<<grid, 256, SMEM_BYTES>>>(Ah, Bh, pv, pi);

    rescore_top3<<<N_ROWS * 32 / 256, 256>>>(pv, pi, An, Bn, out);
}

// round 7
// speedup vs baseline: 6.0394x; 1.0165x over previous
#include <cuda_runtime.h>
#include <cuda_bf16.h>
#include <cstdint>

// ---------------- problem shapes (fixed) ----------------
#define N_ROWS 8192
#define M_ROWS 16384
#define DIM    256

#define BM 128
#define BN 128
#define SPLITS 16
#define BROWS (M_ROWS / SPLITS)     // 1024
#define NBT   (BROWS / BN)          // 8 tiles
#define KCH   64                    // bf16 K-elems per chunk (128B/row)
#define CPT   (DIM / KCH)           // 4 chunks per tile
#define TOTCH (NBT * CPT)           // 32
#define NBUF  4

// smem (uint32 words): A = 128 rows x 128 words; B = 4 bufs x 128 rows x 32 words
#define AW 128
#define BW 32
#define SMEM_WORDS (BM * AW + NBUF * BM * BW)   // 32768
#define SMEM_BYTES (SMEM_WORDS * 4)             // 131072

// ---------------- scratch ----------------
__device__ float          g_An[N_ROWS * DIM];
__device__ float          g_Bn[M_ROWS * DIM];
__device__ __nv_bfloat16  g_Ah[N_ROWS * DIM];
__device__ __nv_bfloat16  g_Bh[M_ROWS * DIM];
__device__ float          g_partv[N_ROWS * SPLITS * 3];
__device__ int            g_parti[N_ROWS * SPLITS * 3];

// ---------------- helpers ----------------
__device__ __forceinline__ uint32_t smem_u32(const void* p) {
    uint32_t a;
    asm("{ .reg .u64 t; cvta.to.shared.u64 t, %1; cvt.u32.u64 %0, t; }" : "=r"(a) : "l"(p));
    return a;
}
__device__ __forceinline__ void cp_async16(uint32_t dst, const void* src) {
    asm volatile("cp.async.cg.shared.global [%0], [%1], 16;" :: "r"(dst), "l"(src));
}
#define CP_COMMIT()  asm volatile("cp.async.commit_group;" ::: "memory")
#define CP_WAIT(n)   asm volatile("cp.async.wait_group %0;" :: "n"(n) : "memory")

__device__ __forceinline__ void ldm_x4(uint32_t* r, uint32_t addr) {
    asm volatile("ldmatrix.sync.aligned.m8n8.x4.shared.b16 {%0,%1,%2,%3}, [%4];"
                 : "=r"(r[0]), "=r"(r[1]), "=r"(r[2]), "=r"(r[3]) : "r"(addr));
}
__device__ __forceinline__ void mma_bf16(float* d, const uint32_t* a, const uint32_t* b) {
    asm volatile(
        "mma.sync.aligned.m16n8k16.row.col.f32.bf16.bf16.f32 "
        "{%0,%1,%2,%3},{%4,%5,%6,%7},{%8,%9},{%0,%1,%2,%3};"
        : "+f"(d[0]), "+f"(d[1]), "+f"(d[2]), "+f"(d[3])
        : "r"(a[0]), "r"(a[1]), "r"(a[2]), "r"(a[3]), "r"(b[0]), "r"(b[1]));
}

// ---------------- row L2 normalization: write fp32 (exact) + bf16 ----------------
__global__ void normalize_rows(const float* __restrict__ in,
                               float* __restrict__ outf,
                               __nv_bfloat16* __restrict__ outh) {
    int row = blockIdx.x, tid = threadIdx.x;
    float v = in[row * DIM + tid];
    float s = v * v;
    #pragma unroll
    for (int o = 16; o > 0; o >>= 1) s += __shfl_xor_sync(0xFFFFFFFFu, s, o);
    __shared__ float red[8];
    if ((tid & 31) == 0) red[tid >> 5] = s;
    __syncthreads();
    __shared__ float tot;
    if (tid < 32) {
        float t = (tid < 8) ? red[tid] : 0.0f;
        #pragma unroll
        for (int o = 4; o > 0; o >>= 1) t += __shfl_xor_sync(0xFFFFFFFFu, t, o);
        if (tid == 0) tot = t;
    }
    __syncthreads();
    float y = v * rsqrtf(tot);
    outf[row * DIM + tid] = y;
    outh[row * DIM + tid] = __float2bfloat16(y);
}

// ---------------- bf16 mma GEMM (ldmatrix) + top-3 with indices ----------------
__global__ void __launch_bounds__(256, 1)
gemm_top3(const __nv_bfloat16* __restrict__ Ah, const __nv_bfloat16* __restrict__ Bh,
          float* __restrict__ partv, int* __restrict__ parti) {
    extern __shared__ uint32_t smem[];
    uint32_t* sA = smem;
    uint32_t* sB = smem + BM * AW;
    const uint32_t sAu = smem_u32(sA);
    const uint32_t sBu = smem_u32(sB);

    const int tid  = threadIdx.x;
    const int w    = tid >> 5, lane = tid & 31;
    const int ty   = lane >> 2, tx = lane & 3;
    const int warpM = w >> 2, warpN = w & 3;

    const int aBase = blockIdx.x * BM;
    const int bBase = blockIdx.y * BROWS;

    // ---- A tile: 128 rows x 256 bf16; word-swizzle iw' = iw ^ ((r&7)<<2) ----
    #pragma unroll 4
    for (int i = tid; i < BM * 32; i += 256) {          // 16B units
        int r = i >> 5, f = i & 31;
        uint32_t dw = (uint32_t)(r * AW + ((4 * f) ^ ((r & 7) << 2)));
        cp_async16(sAu + dw * 4, Ah + (size_t)(aBase + r) * DIM + f * 8);
    }
    CP_COMMIT();

    auto issueB = [&](int c) {
        int t = c >> 2, kc = c & 3, buf = c & 3;
        #pragma unroll 4
        for (int i = tid; i < BM * 8; i += 256) {       // 16B units
            int n = i >> 3, f = i & 7;
            uint32_t dw = (uint32_t)(buf * BM * BW + n * BW + ((4 * f) ^ ((n & 7) << 2)));
            cp_async16(sBu + dw * 4,
                       Bh + (size_t)(bBase + t * BN + n) * DIM + kc * KCH + f * 8);
        }
        CP_COMMIT();
    };

    issueB(0); issueB(1); issueB(2);

    // ---- precompute ldmatrix per-lane addresses ----
    // A: per m-tile, rows warpM*64 + m*16 + (lane&15); k-half = lane>>4
    uint32_t aAddrBase[4], aSw[4];
    {
        int rl = warpM * 64 + (lane & 15);
        #pragma unroll
        for (int m = 0; m < 4; m++) {
            int r = rl + m * 16;
            aAddrBase[m] = sAu + (uint32_t)(r * AW) * 4u;
            aSw[m] = (uint32_t)((r & 7) << 2);
        }
    }
    const uint32_t khA4 = (uint32_t)((lane >> 4) << 2);   // 0 or 4 words
    // B: per p (pair of nt), rows warpN*32 + p*16 + ((lane>>4)<<3) + (lane&7); k-half = (lane>>3)&1
    uint32_t bAddrBase[2], bSw[2];
    {
        int nl = warpN * 32 + ((lane >> 4) << 3) + (lane & 7);
        #pragma unroll
        for (int p = 0; p < 2; p++) {
            int n = nl + p * 16;
            bAddrBase[p] = (uint32_t)(n * BW) * 4u;
            bSw[p] = (uint32_t)((n & 7) << 2);
        }
    }
    const uint32_t khB4 = (uint32_t)(((lane >> 3) & 1) << 2);

    float acc[4][4][4];
    #pragma unroll
    for (int m = 0; m < 4; m++)
        #pragma unroll
        for (int nt = 0; nt < 4; nt++)
            #pragma unroll
            for (int q = 0; q < 4; q++) acc[m][nt][q] = 0.0f;

    float s0[8], s1[8], s2[8];
    int   i0[8], i1[8], i2[8];
    #pragma unroll
    for (int i = 0; i < 8; i++) {
        s0[i] = -2.0f; s1[i] = -2.0f; s2[i] = -2.0f;
        i0[i] = 0; i1[i] = 0; i2[i] = 0;
    }

    for (int c = 0; c < TOTCH; c++) {
        CP_WAIT(2);
        __syncthreads();
        if (c + 3 < TOTCH) issueB(c + 3);
        else CP_COMMIT();

        const uint32_t cb32 = (uint32_t)((c & 3) * 32);          // A k-offset words
        const uint32_t bBufByte = sBu + (uint32_t)((c & 3) * BM * BW) * 4u;

        #pragma unroll
        for (int ks = 0; ks < 4; ks++) {
            const uint32_t ksw = (uint32_t)(ks * 8);
            uint32_t a[4][4];
            #pragma unroll
            for (int m = 0; m < 4; m++) {
                uint32_t woff = cb32 + ((ksw + khA4) ^ aSw[m]);
                ldm_x4(a[m], aAddrBase[m] + (woff << 2));
            }
            uint32_t bq[8];
            #pragma unroll
            for (int p = 0; p < 2; p++) {
                uint32_t woff = (ksw + khB4) ^ bSw[p];
                ldm_x4(&bq[p * 4], bBufByte + ((bAddrBase[p] + (woff << 2))));
            }
            #pragma unroll
            for (int m = 0; m < 4; m++)
                #pragma unroll
                for (int nt = 0; nt < 4; nt++)
                    mma_bf16(acc[m][nt], a[m], &bq[nt * 2]);
        }

        if ((c & 3) == 3) {
            const int tcol = bBase + (c >> 2) * BN + warpN * 32 + tx * 2;
            #pragma unroll
            for (int m = 0; m < 4; m++) {
                #pragma unroll
                for (int h = 0; h < 2; h++) {
                    const int sl = m * 2 + h;
                    float bm = acc[m][0][h * 2];
                    #pragma unroll
                    for (int nt = 0; nt < 4; nt++) {
                        bm = fmaxf(bm, acc[m][nt][h * 2 + 0]);
                        bm = fmaxf(bm, acc[m][nt][h * 2 + 1]);
                    }
                    if (bm > s2[sl]) {
                        #pragma unroll
                        for (int nt = 0; nt < 4; nt++) {
                            #pragma unroll
                            for (int p = 0; p < 2; p++) {
                                float v = acc[m][nt][h * 2 + p];
                                int col = tcol + nt * 8 + p;
                                if (v > s2[sl]) {
                                    if (v > s1[sl]) {
                                        if (v > s0[sl]) {
                                            s2[sl] = s1[sl]; i2[sl] = i1[sl];
                                            s1[sl] = s0[sl]; i1[sl] = i0[sl];
                                            s0[sl] = v;      i0[sl] = col;
                                        } else {
                                            s2[sl] = s1[sl]; i2[sl] = i1[sl];
                                            s1[sl] = v;      i1[sl] = col;
                                        }
                                    } else {
                                        s2[sl] = v; i2[sl] = col;
                                    }
                                }
                            }
                        }
                    }
                }
            }
            #pragma unroll
            for (int m = 0; m < 4; m++)
                #pragma unroll
                for (int nt = 0; nt < 4; nt++)
                    #pragma unroll
                    for (int q = 0; q < 4; q++) acc[m][nt][q] = 0.0f;
        }
    }

    // ---- CTA-level merge: 16 contributors per row -> top-3 (val+idx) ----
    __syncthreads();
    float* candV = (float*)smem;                 // [128][16][3]
    int*   candI = (int*)(smem + 6144);          // [128][16][3]
    #pragma unroll
    for (int m = 0; m < 4; m++) {
        #pragma unroll
        for (int h = 0; h < 2; h++) {
            const int sl = m * 2 + h;
            int row = warpM * 64 + m * 16 + h * 8 + ty;
            int ct  = warpN * 4 + tx;
            int o = (row * 16 + ct) * 3;
            candV[o + 0] = s0[sl]; candV[o + 1] = s1[sl]; candV[o + 2] = s2[sl];
            candI[o + 0] = i0[sl]; candI[o + 1] = i1[sl]; candI[o + 2] = i2[sl];
        }
    }
    __syncthreads();
    if (tid < BM) {
        const float* pv = candV + tid * 48;
        const int*   pi = candI + tid * 48;
        float t0 = -2.0f, t1 = -2.0f, t2 = -2.0f;
        int   j0 = 0, j1 = 0, j2 = 0;
        #pragma unroll
        for (int i = 0; i < 48; i++) {
            float v = pv[i]; int ix = pi[i];
            if (v > t2) {
                if (v > t1) {
                    if (v > t0) { t2 = t1; j2 = j1; t1 = t0; j1 = j0; t0 = v; j0 = ix; }
                    else        { t2 = t1; j2 = j1; t1 = v;  j1 = ix; }
                } else          { t2 = v; j2 = ix; }
            }
        }
        size_t row = (size_t)(blockIdx.x * BM + tid);
        size_t o = (row * SPLITS + blockIdx.y) * 3;
        partv[o + 0] = t0; partv[o + 1] = t1; partv[o + 2] = t2;
        parti[o + 0] = j0; parti[o + 1] = j1; parti[o + 2] = j2;
    }
}

// ---------------- final: top-8 of 48 candidates, exact fp32 rescore, mean top-3 ----
__device__ __forceinline__ unsigned long long mk_key(float v, int idx) {
    uint32_t u = __float_as_uint(v);
    u = (u & 0x80000000u) ? ~u : (u | 0x80000000u);
    return ((unsigned long long)u << 32) | (uint32_t)idx;
}

__global__ void rescore_top3(const float* __restrict__ partv, const int* __restrict__ parti,
                             const float* __restrict__ An, const float* __restrict__ Bn,
                             float* __restrict__ out) {
    const int warp = (blockIdx.x * blockDim.x + threadIdx.x) >> 5;
    const int lane = threadIdx.x & 31;
    if (warp >= N_ROWS) return;
    const int row = warp;

    const float* pv = partv + (size_t)row * 48;
    const int*   pi = parti + (size_t)row * 48;
    unsigned long long k0 = mk_key(pv[lane], pi[lane]);
    unsigned long long k1 = (lane < 16) ? mk_key(pv[32 + lane], pi[32 + lane]) : 0ull;

    int win[8];
    #pragma unroll
    for (int r = 0; r < 8; r++) {
        unsigned long long m = (k0 > k1) ? k0 : k1;
        #pragma unroll
        for (int o = 16; o > 0; o >>= 1) {
            unsigned long long t = __shfl_xor_sync(0xFFFFFFFFu, m, o);
            if (t > m) m = t;
        }
        win[r] = (int)(uint32_t)m;
        if (k0 == m) k0 = 0ull;
        if (k1 == m) k1 = 0ull;
    }

    const float4* a4 = (const float4*)(An + (size_t)row * DIM);
    float4 av0 = a4[lane * 2], av1 = a4[lane * 2 + 1];

    float dots[8];
    #pragma unroll
    for (int j = 0; j < 8; j++) {
        const float4* b4 = (const float4*)(Bn + (size_t)win[j] * DIM);
        float4 b0 = b4[lane * 2], b1 = b4[lane * 2 + 1];
        float p = av0.x * b0.x + av0.y * b0.y + av0.z * b0.z + av0.w * b0.w
                + av1.x * b1.x + av1.y * b1.y + av1.z * b1.z + av1.w * b1.w;
        #pragma unroll
        for (int o = 16; o > 0; o >>= 1) p += __shfl_xor_sync(0xFFFFFFFFu, p, o);
        dots[j] = p;
    }

    if (lane == 0) {
        float t0 = -2.0f, t1 = -2.0f, t2 = -2.0f;
        #pragma unroll
        for (int j = 0; j < 8; j++) {
            float v = dots[j];
            t2 = fmaxf(t2, fminf(v, t1));
            t1 = fmaxf(t1, fminf(v, t0));
            t0 = fmaxf(t0, v);
        }
        out[row] = (t0 + t1 + t2) * (1.0f / 3.0f);
    }
}

// ---------------- launcher ----------------
extern "C" void kernel_launch(void* const* d_in, const int* in_sizes, int n_in,
                              void* d_out, int out_size) {
    const float* A = (const float*)d_in[0];
    const float* B = (const float*)d_in[1];
    float* out = (float*)d_out;

    float* An;  cudaGetSymbolAddress((void**)&An,  g_An);
    float* Bn;  cudaGetSymbolAddress((void**)&Bn,  g_Bn);
    __nv_bfloat16* Ah; cudaGetSymbolAddress((void**)&Ah, g_Ah);
    __nv_bfloat16* Bh; cudaGetSymbolAddress((void**)&Bh, g_Bh);
    float* pv;  cudaGetSymbolAddress((void**)&pv, g_partv);
    int*   pi;  cudaGetSymbolAddress((void**)&pi, g_parti);

    cudaFuncSetAttribute(gemm_top3, cudaFuncAttributeMaxDynamicSharedMemorySize, SMEM_BYTES);

    normalize_rows<<<N_ROWS, DIM>>>(A, An, Ah);
    normalize_rows<<<M_ROWS, DIM>>>(B, Bn, Bh);

    dim3 grid(N_ROWS / BM, SPLITS);
    gemm_top3<<<grid, 256, SMEM_BYTES>>>(Ah, Bh, pv, pi);

    rescore_top3<<<N_ROWS * 32 / 256, 256>>>(pv, pi, An, Bn, out);
}

// round 8
// speedup vs baseline: 7.6653x; 1.2692x over previous
#include <cuda_runtime.h>
#include <cuda_bf16.h>
#include <cstdint>

// ---------------- problem shapes (fixed) ----------------
#define N_ROWS 8192
#define M_ROWS 16384
#define DIM    256

#define BM 64
#define BN 128
#define SPLITS 16
#define BROWS (M_ROWS / SPLITS)     // 1024
#define NBT   (BROWS / BN)          // 8 tiles
#define KCH   64                    // bf16 K-elems per chunk (128B/row)
#define CPT   (DIM / KCH)           // 4 chunks per tile
#define TOTCH (NBT * CPT)           // 32
#define NBUF  4

// smem (uint32 words): A = 64 rows x 128 words (32KB); B = 4 bufs x 128 rows x 32 words (64KB)
#define AW 128
#define BW 32
#define SMEM_WORDS (BM * AW + NBUF * BN * BW)   // 8192 + 16384 = 24576
#define SMEM_BYTES (SMEM_WORDS * 4)             // 98304 (2 CTAs/SM fit in 228KB)

// ---------------- scratch ----------------
__device__ float          g_An[N_ROWS * DIM];
__device__ float          g_Bn[M_ROWS * DIM];
__device__ __nv_bfloat16  g_Ah[N_ROWS * DIM];
__device__ __nv_bfloat16  g_Bh[M_ROWS * DIM];
__device__ float          g_partv[N_ROWS * SPLITS * 3];
__device__ int            g_parti[N_ROWS * SPLITS * 3];

// ---------------- helpers ----------------
__device__ __forceinline__ uint32_t smem_u32(const void* p) {
    uint32_t a;
    asm("{ .reg .u64 t; cvta.to.shared.u64 t, %1; cvt.u32.u64 %0, t; }" : "=r"(a) : "l"(p));
    return a;
}
__device__ __forceinline__ void cp_async16(uint32_t dst, const void* src) {
    asm volatile("cp.async.cg.shared.global [%0], [%1], 16;" :: "r"(dst), "l"(src));
}
#define CP_COMMIT()  asm volatile("cp.async.commit_group;" ::: "memory")
#define CP_WAIT(n)   asm volatile("cp.async.wait_group %0;" :: "n"(n) : "memory")

__device__ __forceinline__ void ldm_x4(uint32_t* r, uint32_t addr) {
    asm volatile("ldmatrix.sync.aligned.m8n8.x4.shared.b16 {%0,%1,%2,%3}, [%4];"
                 : "=r"(r[0]), "=r"(r[1]), "=r"(r[2]), "=r"(r[3]) : "r"(addr));
}
__device__ __forceinline__ void mma_bf16(float* d, const uint32_t* a, const uint32_t* b) {
    asm volatile(
        "mma.sync.aligned.m16n8k16.row.col.f32.bf16.bf16.f32 "
        "{%0,%1,%2,%3},{%4,%5,%6,%7},{%8,%9},{%0,%1,%2,%3};"
        : "+f"(d[0]), "+f"(d[1]), "+f"(d[2]), "+f"(d[3])
        : "r"(a[0]), "r"(a[1]), "r"(a[2]), "r"(a[3]), "r"(b[0]), "r"(b[1]));
}

// ---------------- row L2 normalization: write fp32 (exact) + bf16 ----------------
__global__ void normalize_rows(const float* __restrict__ in,
                               float* __restrict__ outf,
                               __nv_bfloat16* __restrict__ outh) {
    int row = blockIdx.x, tid = threadIdx.x;
    float v = in[row * DIM + tid];
    float s = v * v;
    #pragma unroll
    for (int o = 16; o > 0; o >>= 1) s += __shfl_xor_sync(0xFFFFFFFFu, s, o);
    __shared__ float red[8];
    if ((tid & 31) == 0) red[tid >> 5] = s;
    __syncthreads();
    __shared__ float tot;
    if (tid < 32) {
        float t = (tid < 8) ? red[tid] : 0.0f;
        #pragma unroll
        for (int o = 4; o > 0; o >>= 1) t += __shfl_xor_sync(0xFFFFFFFFu, t, o);
        if (tid == 0) tot = t;
    }
    __syncthreads();
    float y = v * rsqrtf(tot);
    outf[row * DIM + tid] = y;
    outh[row * DIM + tid] = __float2bfloat16(y);
}

// ---------------- bf16 mma GEMM (ldmatrix, occ=2) + top-3 with indices ----------------
__global__ void __launch_bounds__(256, 2)
gemm_top3(const __nv_bfloat16* __restrict__ Ah, const __nv_bfloat16* __restrict__ Bh,
          float* __restrict__ partv, int* __restrict__ parti) {
    extern __shared__ uint32_t smem[];
    uint32_t* sA = smem;
    uint32_t* sB = smem + BM * AW;
    const uint32_t sAu = smem_u32(sA);
    const uint32_t sBu = smem_u32(sB);

    const int tid  = threadIdx.x;
    const int w    = tid >> 5, lane = tid & 31;
    const int ty   = lane >> 2, tx = lane & 3;
    const int warpM = w >> 2, warpN = w & 3;      // 2 x 4 warp grid

    const int aBase = blockIdx.x * BM;
    const int bBase = blockIdx.y * BROWS;

    // ---- A tile: 64 rows x 256 bf16; word-swizzle iw' = iw ^ ((r&7)<<2) ----
    #pragma unroll 4
    for (int i = tid; i < BM * 32; i += 256) {          // 16B units
        int r = i >> 5, f = i & 31;
        uint32_t dw = (uint32_t)(r * AW + ((4 * f) ^ ((r & 7) << 2)));
        cp_async16(sAu + dw * 4, Ah + (size_t)(aBase + r) * DIM + f * 8);
    }
    CP_COMMIT();

    auto issueB = [&](int c) {
        int t = c >> 2, kc = c & 3, buf = c & 3;
        #pragma unroll 4
        for (int i = tid; i < BN * 8; i += 256) {       // 16B units
            int n = i >> 3, f = i & 7;
            uint32_t dw = (uint32_t)(buf * BN * BW + n * BW + ((4 * f) ^ ((n & 7) << 2)));
            cp_async16(sBu + dw * 4,
                       Bh + (size_t)(bBase + t * BN + n) * DIM + kc * KCH + f * 8);
        }
        CP_COMMIT();
    };

    issueB(0); issueB(1); issueB(2);

    // ---- precompute ldmatrix per-lane addresses ----
    uint32_t aAddrBase[2], aSw[2];
    {
        int rl = warpM * 32 + (lane & 15);
        #pragma unroll
        for (int m = 0; m < 2; m++) {
            int r = rl + m * 16;
            aAddrBase[m] = sAu + (uint32_t)(r * AW) * 4u;
            aSw[m] = (uint32_t)((r & 7) << 2);
        }
    }
    const uint32_t khA4 = (uint32_t)((lane >> 4) << 2);
    uint32_t bAddrBase[2], bSw[2];
    {
        int nl = warpN * 32 + ((lane >> 4) << 3) + (lane & 7);
        #pragma unroll
        for (int p = 0; p < 2; p++) {
            int n = nl + p * 16;
            bAddrBase[p] = (uint32_t)(n * BW) * 4u;
            bSw[p] = (uint32_t)((n & 7) << 2);
        }
    }
    const uint32_t khB4 = (uint32_t)(((lane >> 3) & 1) << 2);

    float acc[2][4][4];
    #pragma unroll
    for (int m = 0; m < 2; m++)
        #pragma unroll
        for (int nt = 0; nt < 4; nt++)
            #pragma unroll
            for (int q = 0; q < 4; q++) acc[m][nt][q] = 0.0f;

    float s0[4], s1[4], s2[4];
    int   i0[4], i1[4], i2[4];
    #pragma unroll
    for (int i = 0; i < 4; i++) {
        s0[i] = -2.0f; s1[i] = -2.0f; s2[i] = -2.0f;
        i0[i] = 0; i1[i] = 0; i2[i] = 0;
    }

    for (int c = 0; c < TOTCH; c++) {
        CP_WAIT(2);
        __syncthreads();
        if (c + 3 < TOTCH) issueB(c + 3);
        else CP_COMMIT();

        const uint32_t cb32 = (uint32_t)((c & 3) * 32);
        const uint32_t bBufByte = sBu + (uint32_t)((c & 3) * BN * BW) * 4u;

        #pragma unroll
        for (int ks = 0; ks < 4; ks++) {
            const uint32_t ksw = (uint32_t)(ks * 8);
            uint32_t a[2][4];
            #pragma unroll
            for (int m = 0; m < 2; m++) {
                uint32_t woff = cb32 + ((ksw + khA4) ^ aSw[m]);
                ldm_x4(a[m], aAddrBase[m] + (woff << 2));
            }
            uint32_t bq[8];
            #pragma unroll
            for (int p = 0; p < 2; p++) {
                uint32_t woff = (ksw + khB4) ^ bSw[p];
                ldm_x4(&bq[p * 4], bBufByte + bAddrBase[p] + (woff << 2));
            }
            #pragma unroll
            for (int m = 0; m < 2; m++)
                #pragma unroll
                for (int nt = 0; nt < 4; nt++)
                    mma_bf16(acc[m][nt], a[m], &bq[nt * 2]);
        }

        if ((c & 3) == 3) {
            const int tcol = bBase + (c >> 2) * BN + warpN * 32 + tx * 2;
            #pragma unroll
            for (int m = 0; m < 2; m++) {
                #pragma unroll
                for (int h = 0; h < 2; h++) {
                    const int sl = m * 2 + h;
                    float bm = acc[m][0][h * 2];
                    #pragma unroll
                    for (int nt = 0; nt < 4; nt++) {
                        bm = fmaxf(bm, acc[m][nt][h * 2 + 0]);
                        bm = fmaxf(bm, acc[m][nt][h * 2 + 1]);
                    }
                    if (bm > s2[sl]) {
                        #pragma unroll
                        for (int nt = 0; nt < 4; nt++) {
                            #pragma unroll
                            for (int p = 0; p < 2; p++) {
                                float v = acc[m][nt][h * 2 + p];
                                int col = tcol + nt * 8 + p;
                                if (v > s2[sl]) {
                                    if (v > s1[sl]) {
                                        if (v > s0[sl]) {
                                            s2[sl] = s1[sl]; i2[sl] = i1[sl];
                                            s1[sl] = s0[sl]; i1[sl] = i0[sl];
                                            s0[sl] = v;      i0[sl] = col;
                                        } else {
                                            s2[sl] = s1[sl]; i2[sl] = i1[sl];
                                            s1[sl] = v;      i1[sl] = col;
                                        }
                                    } else {
                                        s2[sl] = v; i2[sl] = col;
                                    }
                                }
                            }
                        }
                    }
                }
            }
            #pragma unroll
            for (int m = 0; m < 2; m++)
                #pragma unroll
                for (int nt = 0; nt < 4; nt++)
                    #pragma unroll
                    for (int q = 0; q < 4; q++) acc[m][nt][q] = 0.0f;
        }
    }

    // ---- CTA-level merge: 16 contributors per row -> top-3 (val+idx) ----
    __syncthreads();
    float* candV = (float*)smem;                 // [64][16][3]
    int*   candI = (int*)(smem + 3072);          // [64][16][3]
    #pragma unroll
    for (int m = 0; m < 2; m++) {
        #pragma unroll
        for (int h = 0; h < 2; h++) {
            const int sl = m * 2 + h;
            int row = warpM * 32 + m * 16 + h * 8 + ty;
            int ct  = warpN * 4 + tx;
            int o = (row * 16 + ct) * 3;
            candV[o + 0] = s0[sl]; candV[o + 1] = s1[sl]; candV[o + 2] = s2[sl];
            candI[o + 0] = i0[sl]; candI[o + 1] = i1[sl]; candI[o + 2] = i2[sl];
        }
    }
    __syncthreads();
    if (tid < BM) {
        const float* pv = candV + tid * 48;
        const int*   pi = candI + tid * 48;
        float t0 = -2.0f, t1 = -2.0f, t2 = -2.0f;
        int   j0 = 0, j1 = 0, j2 = 0;
        #pragma unroll
        for (int i = 0; i < 48; i++) {
            float v = pv[i]; int ix = pi[i];
            if (v > t2) {
                if (v > t1) {
                    if (v > t0) { t2 = t1; j2 = j1; t1 = t0; j1 = j0; t0 = v; j0 = ix; }
                    else        { t2 = t1; j2 = j1; t1 = v;  j1 = ix; }
                } else          { t2 = v; j2 = ix; }
            }
        }
        size_t row = (size_t)(blockIdx.x * BM + tid);
        size_t o = (row * SPLITS + blockIdx.y) * 3;
        partv[o + 0] = t0; partv[o + 1] = t1; partv[o + 2] = t2;
        parti[o + 0] = j0; parti[o + 1] = j1; parti[o + 2] = j2;
    }
}

// ---------------- final: top-8 of 48 candidates, exact fp32 rescore, mean top-3 ----
__device__ __forceinline__ unsigned long long mk_key(float v, int idx) {
    uint32_t u = __float_as_uint(v);
    u = (u & 0x80000000u) ? ~u : (u | 0x80000000u);
    return ((unsigned long long)u << 32) | (uint32_t)idx;
}

__global__ void rescore_top3(const float* __restrict__ partv, const int* __restrict__ parti,
                             const float* __restrict__ An, const float* __restrict__ Bn,
                             float* __restrict__ out) {
    const int warp = (blockIdx.x * blockDim.x + threadIdx.x) >> 5;
    const int lane = threadIdx.x & 31;
    if (warp >= N_ROWS) return;
    const int row = warp;

    const float* pv = partv + (size_t)row * 48;
    const int*   pi = parti + (size_t)row * 48;
    unsigned long long k0 = mk_key(pv[lane], pi[lane]);
    unsigned long long k1 = (lane < 16) ? mk_key(pv[32 + lane], pi[32 + lane]) : 0ull;

    int win[8];
    #pragma unroll
    for (int r = 0; r < 8; r++) {
        unsigned long long m = (k0 > k1) ? k0 : k1;
        #pragma unroll
        for (int o = 16; o > 0; o >>= 1) {
            unsigned long long t = __shfl_xor_sync(0xFFFFFFFFu, m, o);
            if (t > m) m = t;
        }
        win[r] = (int)(uint32_t)m;
        if (k0 == m) k0 = 0ull;
        if (k1 == m) k1 = 0ull;
    }

    const float4* a4 = (const float4*)(An + (size_t)row * DIM);
    float4 av0 = a4[lane * 2], av1 = a4[lane * 2 + 1];

    float dots[8];
    #pragma unroll
    for (int j = 0; j < 8; j++) {
        const float4* b4 = (const float4*)(Bn + (size_t)win[j] * DIM);
        float4 b0 = b4[lane * 2], b1 = b4[lane * 2 + 1];
        float p = av0.x * b0.x + av0.y * b0.y + av0.z * b0.z + av0.w * b0.w
                + av1.x * b1.x + av1.y * b1.y + av1.z * b1.z + av1.w * b1.w;
        #pragma unroll
        for (int o = 16; o > 0; o >>= 1) p += __shfl_xor_sync(0xFFFFFFFFu, p, o);
        dots[j] = p;
    }

    if (lane == 0) {
        float t0 = -2.0f, t1 = -2.0f, t2 = -2.0f;
        #pragma unroll
        for (int j = 0; j < 8; j++) {
            float v = dots[j];
            t2 = fmaxf(t2, fminf(v, t1));
            t1 = fmaxf(t1, fminf(v, t0));
            t0 = fmaxf(t0, v);
        }
        out[row] = (t0 + t1 + t2) * (1.0f / 3.0f);
    }
}

// ---------------- launcher ----------------
extern "C" void kernel_launch(void* const* d_in, const int* in_sizes, int n_in,
                              void* d_out, int out_size) {
    const float* A = (const float*)d_in[0];
    const float* B = (const float*)d_in[1];
    float* out = (float*)d_out;

    float* An;  cudaGetSymbolAddress((void**)&An,  g_An);
    float* Bn;  cudaGetSymbolAddress((void**)&Bn,  g_Bn);
    __nv_bfloat16* Ah; cudaGetSymbolAddress((void**)&Ah, g_Ah);
    __nv_bfloat16* Bh; cudaGetSymbolAddress((void**)&Bh, g_Bh);
    float* pv;  cudaGetSymbolAddress((void**)&pv, g_partv);
    int*   pi;  cudaGetSymbolAddress((void**)&pi, g_parti);

    cudaFuncSetAttribute(gemm_top3, cudaFuncAttributeMaxDynamicSharedMemorySize, SMEM_BYTES);

    normalize_rows<<<N_ROWS, DIM>>>(A, An, Ah);
    normalize_rows<<<M_ROWS, DIM>>>(B, Bn, Bh);

    dim3 grid(N_ROWS / BM, SPLITS);
    gemm_top3<<<grid, 256, SMEM_BYTES>>>(Ah, Bh, pv, pi);

    rescore_top3<<<N_ROWS * 32 / 256, 256>>>(pv, pi, An, Bn, out);
}